// round 3
// baseline (speedup 1.0000x reference)
#include <cuda_runtime.h>
#include <math.h>

#define NTHREADS 256
#define OPT 16                      // outputs per thread
#define TILE (NTHREADS * OPT)       // 4096 samples per block
#define NTAPS 5
#define NSAMP 131072
#define BATCH 64
#define FS_F 30720000.0f
#define SCS_F 15000.0f
#define MAX_CFO_F 0.05f
#define TWO_PI_F 6.28318530717958647692f

__global__ __launch_bounds__(NTHREADS)
void wireless_channel_kernel(
    const float* __restrict__ x_real,  const float* __restrict__ x_imag,
    const float* __restrict__ ebno_db, const float* __restrict__ cfo_u,
    const float* __restrict__ taps_real, const float* __restrict__ taps_imag,
    const float* __restrict__ noise_real, const float* __restrict__ noise_imag,
    float* __restrict__ out)
{
    const int b  = blockIdx.y;
    const int n0 = blockIdx.x * TILE + threadIdx.x * OPT;  // first output sample

    // ---- per-row scalars (broadcast loads) ----
    const float cfo    = cfo_u[b];
    const float deltaf = (cfo * 2.0f - 1.0f) * MAX_CFO_F * SCS_F;
    const float w      = (TWO_PI_F * deltaf) / FS_F;          // rad / sample
    const float snr    = ebno_db[b] + 1.7609125905568124f;    // +10*log10(1.5)
    const float scale  = 0.5f * exp2f(-snr * 0.16609640474436813f); // 10^(-snr/20)

    float tr[NTAPS], ti[NTAPS];
    #pragma unroll
    for (int k = 0; k < NTAPS; k++) {
        tr[k] = taps_real[b * NTAPS + k];
        ti[k] = taps_imag[b * NTAPS + k];
    }

    const float* __restrict__ xr_row = x_real + (size_t)b * NSAMP;
    const float* __restrict__ xi_row = x_imag + (size_t)b * NSAMP;

    // ---- fetch raw window: need samples [n0-2, n0+OPT+1]; fast path loads the
    //      16B-aligned superset [n0-4, n0+OPT+4) as 6x float4 per array.
    float xrb[OPT + 8], xib[OPT + 8];
    if (n0 >= 4 && n0 + OPT + 4 <= NSAMP) {
        const float4* __restrict__ xr4 = (const float4*)(xr_row + n0 - 4);
        const float4* __restrict__ xi4 = (const float4*)(xi_row + n0 - 4);
        #pragma unroll
        for (int v = 0; v < (OPT + 8) / 4; v++) {
            ((float4*)xrb)[v] = xr4[v];
            ((float4*)xib)[v] = xi4[v];
        }
    } else {
        // row-edge lanes: scalar loads with zero padding
        #pragma unroll
        for (int i = 0; i < OPT + 8; i++) {
            const int g = n0 - 4 + i;
            float xr = 0.0f, xi = 0.0f;
            if (g >= 0 && g < NSAMP) { xr = xr_row[g]; xi = xi_row[g]; }
            xrb[i] = xr; xib[i] = xi;
        }
    }

    // ---- noise (vectorized, n0 is 64B-aligned) ----
    const float4* __restrict__ nr4 = (const float4*)(noise_real + (size_t)b * NSAMP + n0);
    const float4* __restrict__ ni4 = (const float4*)(noise_imag + (size_t)b * NSAMP + n0);
    float4 nr[OPT / 4], ni[OPT / 4];
    #pragma unroll
    for (int v = 0; v < OPT / 4; v++) { nr[v] = nr4[v]; ni[v] = ni4[v]; }
    const float* nrp = (const float*)nr;
    const float* nip = (const float*)ni;

    // ---- CFO rotation of window [n0-2, n0+OPT+1] via phase recurrence ----
    float rxr[OPT + 4], rxi[OPT + 4];
    float s, c, sw, cw;
    __sincosf(w * (float)(n0 - 2), &s, &c);   // phase at first halo sample
    __sincosf(w, &sw, &cw);                   // per-sample rotation step

    #pragma unroll
    for (int i = 0; i < OPT + 4; i++) {
        const float xr = xrb[i + 2];
        const float xi = xib[i + 2];
        rxr[i] = xr * c - xi * s;
        rxi[i] = xr * s + xi * c;
        const float c2 = c * cw - s * sw;     // advance phase by w
        const float s2 = c * sw + s * cw;
        c = c2; s = s2;
    }

    // ---- 5-tap complex conv + AWGN + vectorized stores ----
    float4* outr = (float4*)(out + (size_t)b * NSAMP + n0);
    float4* outi = (float4*)(out + (size_t)BATCH * NSAMP + (size_t)b * NSAMP + n0);

    #pragma unroll
    for (int v = 0; v < OPT / 4; v++) {
        float yr[4], yi[4];
        #pragma unroll
        for (int u = 0; u < 4; u++) {
            const int j = v * 4 + u;
            float s_rr = 0.0f, s_ii = 0.0f, s_ri = 0.0f, s_ir = 0.0f;
            #pragma unroll
            for (int k = 0; k < NTAPS; k++) {
                s_rr = fmaf(tr[k], rxr[j + k], s_rr);
                s_ii = fmaf(ti[k], rxi[j + k], s_ii);
                s_ir = fmaf(ti[k], rxr[j + k], s_ir);
                s_ri = fmaf(tr[k], rxi[j + k], s_ri);
            }
            yr[u] = (s_rr - s_ii) + nrp[j] * scale;
            yi[u] = (s_ir + s_ri) + nip[j] * scale;
        }
        outr[v] = make_float4(yr[0], yr[1], yr[2], yr[3]);
        outi[v] = make_float4(yi[0], yi[1], yi[2], yi[3]);
    }
}

extern "C" void kernel_launch(void* const* d_in, const int* in_sizes, int n_in,
                              void* d_out, int out_size)
{
    const float* x_real     = (const float*)d_in[0];
    const float* x_imag     = (const float*)d_in[1];
    const float* ebno_db    = (const float*)d_in[2];
    const float* cfo_u      = (const float*)d_in[3];
    const float* taps_real  = (const float*)d_in[4];
    const float* taps_imag  = (const float*)d_in[5];
    const float* noise_real = (const float*)d_in[6];
    const float* noise_imag = (const float*)d_in[7];
    float* out = (float*)d_out;

    dim3 grid(NSAMP / TILE, BATCH);   // (32, 64)
    wireless_channel_kernel<<<grid, NTHREADS>>>(
        x_real, x_imag, ebno_db, cfo_u, taps_real, taps_imag,
        noise_real, noise_imag, out);
}

// round 4
// speedup vs baseline: 1.0556x; 1.0556x over previous
#include <cuda_runtime.h>
#include <math.h>

#define NTHREADS 256
#define OPT 8                       // outputs per thread
#define TILE (NTHREADS * OPT)       // 2048 samples per block
#define NTAPS 5
#define NSAMP 131072
#define BATCH 64
#define FS_F 30720000.0f
#define SCS_F 15000.0f
#define MAX_CFO_F 0.05f
#define TWO_PI_F 6.28318530717958647692f

__global__ __launch_bounds__(NTHREADS, 6)
void wireless_channel_kernel(
    const float* __restrict__ x_real,  const float* __restrict__ x_imag,
    const float* __restrict__ ebno_db, const float* __restrict__ cfo_u,
    const float* __restrict__ taps_real, const float* __restrict__ taps_imag,
    const float* __restrict__ noise_real, const float* __restrict__ noise_imag,
    float* __restrict__ out)
{
    const int b  = blockIdx.y;
    const int n0 = blockIdx.x * TILE + threadIdx.x * OPT;  // first output sample

    // ================== front-batched global loads (max MLP) ==================
    // x window superset [n0-4, n0+12), 16B-aligned: 4x LDG.128 per array
    float xrb[16], xib[16];
    const float* __restrict__ xr_row = x_real + (size_t)b * NSAMP;
    const float* __restrict__ xi_row = x_imag + (size_t)b * NSAMP;
    const bool interior = (n0 >= 4) && (n0 + 12 <= NSAMP);
    if (interior) {
        const float4* __restrict__ xr4 = (const float4*)(xr_row + n0 - 4);
        const float4* __restrict__ xi4 = (const float4*)(xi_row + n0 - 4);
        #pragma unroll
        for (int v = 0; v < 4; v++) {
            ((float4*)xrb)[v] = xr4[v];
            ((float4*)xib)[v] = xi4[v];
        }
    }

    // noise: streaming (no reuse) — evict-first
    const float4* __restrict__ nr4 = (const float4*)(noise_real + (size_t)b * NSAMP + n0);
    const float4* __restrict__ ni4 = (const float4*)(noise_imag + (size_t)b * NSAMP + n0);
    float4 nr[2], ni[2];
    nr[0] = __ldcs(nr4 + 0); nr[1] = __ldcs(nr4 + 1);
    ni[0] = __ldcs(ni4 + 0); ni[1] = __ldcs(ni4 + 1);
    const float* nrp = (const float*)nr;
    const float* nip = (const float*)ni;

    // row-edge lanes (2 per row): scalar zero-padded fallback
    if (!interior) {
        #pragma unroll
        for (int i = 0; i < 16; i++) {
            const int g = n0 - 4 + i;
            float xr = 0.0f, xi = 0.0f;
            if (g >= 0 && g < NSAMP) { xr = xr_row[g]; xi = xi_row[g]; }
            xrb[i] = xr; xib[i] = xi;
        }
    }

    // ================== per-row scalars ==================
    const float cfo    = cfo_u[b];
    const float deltaf = (cfo * 2.0f - 1.0f) * MAX_CFO_F * SCS_F;
    const float w      = (TWO_PI_F * deltaf) / FS_F;          // rad / sample
    const float snr    = ebno_db[b] + 1.7609125905568124f;    // +10*log10(1.5)
    const float scale  = 0.5f * exp2f(-snr * 0.16609640474436813f); // 10^(-snr/20)

    float tr[NTAPS], ti[NTAPS];
    #pragma unroll
    for (int k = 0; k < NTAPS; k++) {
        tr[k] = taps_real[b * NTAPS + k];
        ti[k] = taps_imag[b * NTAPS + k];
    }

    // ======= CFO rotation of window [n0-2, n0+9] via phase recurrence =======
    // Rotate in place (overwrite xrb/xib) to keep live-register count low.
    float s, c, sw, cw;
    __sincosf(w * (float)(n0 - 2), &s, &c);   // phase at first halo sample
    __sincosf(w, &sw, &cw);                   // per-sample rotation step

    #pragma unroll
    for (int i = 2; i < 14; i++) {
        const float xr = xrb[i];
        const float xi = xib[i];
        xrb[i] = xr * c - xi * s;
        xib[i] = xr * s + xi * c;
        const float c2 = c * cw - s * sw;     // advance phase by w
        const float s2 = c * sw + s * cw;
        c = c2; s = s2;
    }

    // ============ 5-tap complex conv + AWGN + streaming stores ============
    float4* outr = (float4*)(out + (size_t)b * NSAMP + n0);
    float4* outi = (float4*)(out + (size_t)BATCH * NSAMP + (size_t)b * NSAMP + n0);

    #pragma unroll
    for (int v = 0; v < 2; v++) {
        float4 or4, oi4;
        float* orp = (float*)&or4;
        float* oip = (float*)&oi4;
        #pragma unroll
        for (int u = 0; u < 4; u++) {
            const int j = v * 4 + u;
            float s_rr = 0.0f, s_ii = 0.0f, s_ri = 0.0f, s_ir = 0.0f;
            #pragma unroll
            for (int k = 0; k < NTAPS; k++) {
                s_rr = fmaf(tr[k], xrb[j + k + 2], s_rr);
                s_ii = fmaf(ti[k], xib[j + k + 2], s_ii);
                s_ir = fmaf(ti[k], xrb[j + k + 2], s_ir);
                s_ri = fmaf(tr[k], xib[j + k + 2], s_ri);
            }
            orp[u] = (s_rr - s_ii) + nrp[j] * scale;
            oip[u] = (s_ir + s_ri) + nip[j] * scale;
        }
        __stcs(outr + v, or4);
        __stcs(outi + v, oi4);
    }
}

extern "C" void kernel_launch(void* const* d_in, const int* in_sizes, int n_in,
                              void* d_out, int out_size)
{
    const float* x_real     = (const float*)d_in[0];
    const float* x_imag     = (const float*)d_in[1];
    const float* ebno_db    = (const float*)d_in[2];
    const float* cfo_u      = (const float*)d_in[3];
    const float* taps_real  = (const float*)d_in[4];
    const float* taps_imag  = (const float*)d_in[5];
    const float* noise_real = (const float*)d_in[6];
    const float* noise_imag = (const float*)d_in[7];
    float* out = (float*)d_out;

    dim3 grid(NSAMP / TILE, BATCH);   // (64, 64)
    wireless_channel_kernel<<<grid, NTHREADS>>>(
        x_real, x_imag, ebno_db, cfo_u, taps_real, taps_imag,
        noise_real, noise_imag, out);
}

// round 5
// speedup vs baseline: 1.1722x; 1.1105x over previous
#include <cuda_runtime.h>
#include <math.h>

#define NTHREADS 256
#define OPT 8                       // outputs per thread
#define TILE (NTHREADS * OPT)       // 2048 samples per block
#define NTAPS 5
#define NSAMP 131072
#define BATCH 64
#define FS_F 30720000.0f
#define SCS_F 15000.0f
#define MAX_CFO_F 0.05f
#define TWO_PI_F 6.28318530717958647692f

__global__ __launch_bounds__(NTHREADS)
void wireless_channel_kernel(
    const float* __restrict__ x_real,  const float* __restrict__ x_imag,
    const float* __restrict__ ebno_db, const float* __restrict__ cfo_u,
    const float* __restrict__ taps_real, const float* __restrict__ taps_imag,
    const float* __restrict__ noise_real, const float* __restrict__ noise_imag,
    float* __restrict__ out)
{
    const int b  = blockIdx.y;
    const int n0 = blockIdx.x * TILE + threadIdx.x * OPT;  // first output sample

    const float* __restrict__ xr_row = x_real + (size_t)b * NSAMP;
    const float* __restrict__ xi_row = x_imag + (size_t)b * NSAMP;

    // ============ front-batched global loads: 12x LDG.128 in one burst ============
    // x window superset [n0-4, n0+12), 16B-aligned: 4x float4 per array
    float xrb[16], xib[16];
    float4 nr[2], ni[2];
    const float4* __restrict__ nr4 = (const float4*)(noise_real + (size_t)b * NSAMP + n0);
    const float4* __restrict__ ni4 = (const float4*)(noise_imag + (size_t)b * NSAMP + n0);
    const bool interior = (n0 >= 4) && (n0 + 12 <= NSAMP);
    if (interior) {
        const float4* __restrict__ xr4 = (const float4*)(xr_row + n0 - 4);
        const float4* __restrict__ xi4 = (const float4*)(xi_row + n0 - 4);
        #pragma unroll
        for (int v = 0; v < 4; v++) {
            ((float4*)xrb)[v] = xr4[v];
            ((float4*)xib)[v] = xi4[v];
        }
        nr[0] = nr4[0]; nr[1] = nr4[1];
        ni[0] = ni4[0]; ni[1] = ni4[1];
    } else {
        // row-edge lanes (2 per row): scalar zero-padded fallback
        #pragma unroll
        for (int i = 0; i < 16; i++) {
            const int g = n0 - 4 + i;
            float xr = 0.0f, xi = 0.0f;
            if (g >= 0 && g < NSAMP) { xr = xr_row[g]; xi = xi_row[g]; }
            xrb[i] = xr; xib[i] = xi;
        }
        nr[0] = nr4[0]; nr[1] = nr4[1];
        ni[0] = ni4[0]; ni[1] = ni4[1];
    }
    const float* nrp = (const float*)nr;
    const float* nip = (const float*)ni;

    // ================== per-row scalars (broadcast loads) ==================
    const float cfo    = cfo_u[b];
    const float deltaf = (cfo * 2.0f - 1.0f) * MAX_CFO_F * SCS_F;
    const float w      = (TWO_PI_F * deltaf) / FS_F;          // rad / sample
    const float snr    = ebno_db[b] + 1.7609125905568124f;    // +10*log10(1.5)
    const float scale  = 0.5f * exp2f(-snr * 0.16609640474436813f); // 10^(-snr/20)

    float tr[NTAPS], ti[NTAPS];
    #pragma unroll
    for (int k = 0; k < NTAPS; k++) {
        tr[k] = taps_real[b * NTAPS + k];
        ti[k] = taps_imag[b * NTAPS + k];
    }

    // ======= CFO rotation of window [n0-2, n0+9] via phase recurrence =======
    float rxr[OPT + 4], rxi[OPT + 4];
    float s, c, sw, cw;
    __sincosf(w * (float)(n0 - 2), &s, &c);   // phase at first halo sample
    __sincosf(w, &sw, &cw);                   // per-sample rotation step

    #pragma unroll
    for (int i = 0; i < OPT + 4; i++) {
        const float xr = xrb[i + 2];
        const float xi = xib[i + 2];
        rxr[i] = xr * c - xi * s;
        rxi[i] = xr * s + xi * c;
        const float c2 = c * cw - s * sw;     // advance phase by w
        const float s2 = c * sw + s * cw;
        c = c2; s = s2;
    }

    // ============ 5-tap complex conv + AWGN + vectorized stores ============
    float yr[OPT], yi[OPT];
    #pragma unroll
    for (int j = 0; j < OPT; j++) {
        float s_rr = 0.0f, s_ii = 0.0f, s_ri = 0.0f, s_ir = 0.0f;
        #pragma unroll
        for (int k = 0; k < NTAPS; k++) {
            s_rr = fmaf(tr[k], rxr[j + k], s_rr);
            s_ii = fmaf(ti[k], rxi[j + k], s_ii);
            s_ir = fmaf(ti[k], rxr[j + k], s_ir);
            s_ri = fmaf(tr[k], rxi[j + k], s_ri);
        }
        yr[j] = (s_rr - s_ii) + nrp[j] * scale;
        yi[j] = (s_ir + s_ri) + nip[j] * scale;
    }

    float4* outr = (float4*)(out + (size_t)b * NSAMP + n0);
    float4* outi = (float4*)(out + (size_t)BATCH * NSAMP + (size_t)b * NSAMP + n0);
    outr[0] = make_float4(yr[0], yr[1], yr[2], yr[3]);
    outr[1] = make_float4(yr[4], yr[5], yr[6], yr[7]);
    outi[0] = make_float4(yi[0], yi[1], yi[2], yi[3]);
    outi[1] = make_float4(yi[4], yi[5], yi[6], yi[7]);
}

extern "C" void kernel_launch(void* const* d_in, const int* in_sizes, int n_in,
                              void* d_out, int out_size)
{
    const float* x_real     = (const float*)d_in[0];
    const float* x_imag     = (const float*)d_in[1];
    const float* ebno_db    = (const float*)d_in[2];
    const float* cfo_u      = (const float*)d_in[3];
    const float* taps_real  = (const float*)d_in[4];
    const float* taps_imag  = (const float*)d_in[5];
    const float* noise_real = (const float*)d_in[6];
    const float* noise_imag = (const float*)d_in[7];
    float* out = (float*)d_out;

    dim3 grid(NSAMP / TILE, BATCH);   // (64, 64)
    wireless_channel_kernel<<<grid, NTHREADS>>>(
        x_real, x_imag, ebno_db, cfo_u, taps_real, taps_imag,
        noise_real, noise_imag, out);
}

// round 6
// speedup vs baseline: 1.3154x; 1.1221x over previous
#include <cuda_runtime.h>
#include <math.h>

#define NTHREADS 256
#define OPT 8                       // outputs per thread
#define TILE (NTHREADS * OPT)       // 2048 samples per block
#define NTAPS 5
#define NSAMP 131072
#define BATCH 64
#define FS_F 30720000.0f
#define SCS_F 15000.0f
#define MAX_CFO_F 0.05f
#define TWO_PI_F 6.28318530717958647692f

__global__ __launch_bounds__(NTHREADS, 6)
void wireless_channel_kernel(
    const float* __restrict__ x_real,  const float* __restrict__ x_imag,
    const float* __restrict__ ebno_db, const float* __restrict__ cfo_u,
    const float* __restrict__ taps_real, const float* __restrict__ taps_imag,
    const float* __restrict__ noise_real, const float* __restrict__ noise_imag,
    float* __restrict__ out)
{
    const int b    = blockIdx.y;
    const int n0   = blockIdx.x * TILE + threadIdx.x * OPT;  // first output sample

    // ---- per-row scalars (broadcast loads) ----
    const float cfo    = cfo_u[b];
    const float deltaf = (cfo * 2.0f - 1.0f) * MAX_CFO_F * SCS_F;
    const float w      = (TWO_PI_F * deltaf) / FS_F;          // rad / sample
    // snr_db = ebno + 10*log10(1.5); scale = 0.5 * 10^(-snr/20)
    const float snr    = ebno_db[b] + 1.7609125905568124f;
    const float scale  = 0.5f * exp2f(-snr * 0.16609640474436813f); // log2(10)/20

    float tr[NTAPS], ti[NTAPS];
    #pragma unroll
    for (int k = 0; k < NTAPS; k++) {
        tr[k] = taps_real[b * NTAPS + k];
        ti[k] = taps_imag[b * NTAPS + k];
    }

    const float* __restrict__ xr_row = x_real + (size_t)b * NSAMP;
    const float* __restrict__ xi_row = x_imag + (size_t)b * NSAMP;

    // ---- fetch raw window: need samples [n0-2, n0+9]; fast path loads the
    //      16B-aligned superset [n0-4, n0+12) as 4x float4 per array.
    float xrb[16], xib[16];
    if (n0 >= 4 && n0 + 12 <= NSAMP) {
        const float4* __restrict__ xr4 = (const float4*)(xr_row + n0 - 4);
        const float4* __restrict__ xi4 = (const float4*)(xi_row + n0 - 4);
        #pragma unroll
        for (int v = 0; v < 4; v++) {
            ((float4*)xrb)[v] = xr4[v];
            ((float4*)xib)[v] = xi4[v];
        }
    } else {
        // row-edge lanes: scalar loads with zero padding (2 lanes per row)
        #pragma unroll
        for (int i = 0; i < 16; i++) {
            const int g = n0 - 4 + i;
            float xr = 0.0f, xi = 0.0f;
            if (g >= 0 && g < NSAMP) { xr = xr_row[g]; xi = xi_row[g]; }
            xrb[i] = xr; xib[i] = xi;
        }
    }

    // ---- CFO rotation of window [n0-2, n0+9] via phase recurrence ----
    float rxr[OPT + 4], rxi[OPT + 4];
    float s, c, sw, cw;
    __sincosf(w * (float)(n0 - 2), &s, &c);   // phase at first halo sample
    __sincosf(w, &sw, &cw);                   // per-sample rotation step

    #pragma unroll
    for (int i = 0; i < OPT + 4; i++) {
        const float xr = xrb[i + 2];
        const float xi = xib[i + 2];
        rxr[i] = xr * c - xi * s;
        rxi[i] = xr * s + xi * c;
        const float c2 = c * cw - s * sw;     // advance phase by w
        const float s2 = c * sw + s * cw;
        c = c2; s = s2;
    }

    // ---- noise (vectorized, n0 is 32B-aligned) ----
    const float4* __restrict__ nr4 = (const float4*)(noise_real + (size_t)b * NSAMP + n0);
    const float4* __restrict__ ni4 = (const float4*)(noise_imag + (size_t)b * NSAMP + n0);
    float4 nr[2] = { nr4[0], nr4[1] };
    float4 ni[2] = { ni4[0], ni4[1] };
    const float* nrp = (const float*)nr;
    const float* nip = (const float*)ni;

    // ---- 5-tap complex conv + AWGN ----
    float yr[OPT], yi[OPT];
    #pragma unroll
    for (int j = 0; j < OPT; j++) {
        float s_rr = 0.0f, s_ii = 0.0f, s_ri = 0.0f, s_ir = 0.0f;
        #pragma unroll
        for (int k = 0; k < NTAPS; k++) {
            s_rr = fmaf(tr[k], rxr[j + k], s_rr);
            s_ii = fmaf(ti[k], rxi[j + k], s_ii);
            s_ir = fmaf(ti[k], rxr[j + k], s_ir);
            s_ri = fmaf(tr[k], rxi[j + k], s_ri);
        }
        yr[j] = (s_rr - s_ii) + nrp[j] * scale;
        yi[j] = (s_ir + s_ri) + nip[j] * scale;
    }

    // ---- vectorized stores: out[0,b,:] = real, out[1,b,:] = imag ----
    float4* outr = (float4*)(out + (size_t)b * NSAMP + n0);
    float4* outi = (float4*)(out + (size_t)BATCH * NSAMP + (size_t)b * NSAMP + n0);
    outr[0] = make_float4(yr[0], yr[1], yr[2], yr[3]);
    outr[1] = make_float4(yr[4], yr[5], yr[6], yr[7]);
    outi[0] = make_float4(yi[0], yi[1], yi[2], yi[3]);
    outi[1] = make_float4(yi[4], yi[5], yi[6], yi[7]);
}

extern "C" void kernel_launch(void* const* d_in, const int* in_sizes, int n_in,
                              void* d_out, int out_size)
{
    const float* x_real     = (const float*)d_in[0];
    const float* x_imag     = (const float*)d_in[1];
    const float* ebno_db    = (const float*)d_in[2];
    const float* cfo_u      = (const float*)d_in[3];
    const float* taps_real  = (const float*)d_in[4];
    const float* taps_imag  = (const float*)d_in[5];
    const float* noise_real = (const float*)d_in[6];
    const float* noise_imag = (const float*)d_in[7];
    float* out = (float*)d_out;

    dim3 grid(NSAMP / TILE, BATCH);   // (64, 64)
    wireless_channel_kernel<<<grid, NTHREADS>>>(
        x_real, x_imag, ebno_db, cfo_u, taps_real, taps_imag,
        noise_real, noise_imag, out);
}